// round 7
// baseline (speedup 1.0000x reference)
#include <cuda_runtime.h>
#include <cstdint>

// Problem constants
#define B_    8
#define C_    256
#define L_    1024
#define BL    8192            // B*L rows
#define D_IN  512
#define D_ST  16
#define DT_R  16
#define PAD   17

__device__ __forceinline__ uint32_t to_tf32(float v) {
    uint32_t r; asm("cvt.rna.tf32.f32 %0, %1;" : "=r"(r) : "f"(v)); return r;
}
// m16n8k8 tf32 MMA, D += A*B
__device__ __forceinline__ void mma8(float* d, const uint32_t* a, const uint32_t* b) {
    asm volatile(
        "mma.sync.aligned.m16n8k8.row.col.f32.tf32.tf32.f32 "
        "{%0,%1,%2,%3}, {%4,%5,%6,%7}, {%8,%9}, {%0,%1,%2,%3};"
        : "+f"(d[0]), "+f"(d[1]), "+f"(d[2]), "+f"(d[3])
        : "r"(a[0]), "r"(a[1]), "r"(a[2]), "r"(a[3]), "r"(b[0]), "r"(b[1]));
}

// ---------------- scratch (static __device__, no allocation) ----------------
__device__ __align__(16) float g_xz[BL * 1024];    // [row, 0:512]=xs_pre, [512:1024]=z
__device__ __align__(16) float g_xs[BL * D_IN];    // post conv+silu
__device__ __align__(16) float g_dt[BL * D_IN];
__device__ __align__(16) float g_bc[BL * 32];      // packed [Bm(16), Cm(16)]
__device__ __align__(16) float g_yact[BL * D_IN];  // (ys + xs*Dp)*silu(z)

// ---------------- 1. GEMM1 (tf32 mma.sync) with fused LayerNorm stats ----------------
// M=8192, N=1024, K=256. CTA 128x128, 8 warps (4m x 2n), warp 32x64, BK=16.
__global__ __launch_bounds__(256) void gemm1_mma_kernel(
    const float* __restrict__ x, const float* __restrict__ ln_w,
    const float* __restrict__ ln_b, const float* __restrict__ W_in) {
    __shared__ uint32_t As[2][128][PAD];   // [m][k] tf32 bits
    __shared__ uint32_t Bsm[2][128][PAD];  // [n][k] tf32 bits
    __shared__ float muS[128], rsS[128], lwS[C_], lbS[C_];
    __shared__ float red[2][128][2];

    const int tid  = threadIdx.x;
    const int wid  = tid >> 5;
    const int lane = tid & 31;
    const int n0   = blockIdx.x * 128;
    const int row0 = blockIdx.y * 128;
    const int b    = row0 >> 10;
    const int l0   = row0 & 1023;

    // ---- fused LN stats: each of 256 threads sums over half of C for one row ----
    {
        int m  = tid & 127;
        int cg = tid >> 7;
        float s = 0.f, q = 0.f;
        const float* xb = x + ((size_t)(b * C_ + cg)) * L_ + l0 + m;
#pragma unroll 8
        for (int c = 0; c < 128; ++c) {
            float v = xb[(size_t)c * 2 * L_];
            s += v; q += v * v;
        }
        red[cg][m][0] = s; red[cg][m][1] = q;
    }
    lwS[tid] = ln_w[tid]; lbS[tid] = ln_b[tid];
    __syncthreads();
    if (tid < 128) {
        float s = red[0][tid][0] + red[1][tid][0];
        float q = red[0][tid][1] + red[1][tid][1];
        float m   = s * (1.f / C_);
        float var = q * (1.f / C_) - m * m;
        muS[tid] = m;
        rsS[tid] = rsqrtf(var + 1e-5f);
    }
    __syncthreads();

    const int q = lane >> 2, r = lane & 3;
    const int wm = (wid >> 1) * 32, wn = (wid & 1) * 64;

    float ra[8], rb[8];
    auto gload = [&](int kc) {
#pragma unroll
        for (int i = 0; i < 8; ++i) {
            int e = tid + i * 256;
            int m = e & 127, k = e >> 7;
            ra[i] = x[((size_t)(b * C_ + kc + k)) * L_ + l0 + m];
            int n = e & 127;   // same decomposition for B
            rb[i] = W_in[(size_t)(kc + k) * 1024 + n0 + n];
        }
    };
    auto sstore = [&](int buf, int kc) {
#pragma unroll
        for (int i = 0; i < 8; ++i) {
            int e = tid + i * 256;
            int m = e & 127, k = e >> 7;
            int c = kc + k;
            As[buf][m][k]  = to_tf32((ra[i] - muS[m]) * rsS[m] * lwS[c] + lbS[c]);
            Bsm[buf][m][k] = to_tf32(rb[i]);
        }
    };

    float acc[2][8][4] = {};
    gload(0);
    sstore(0, 0);
    __syncthreads();

    const int NIT = C_ / 16;  // 16
    for (int it = 0; it < NIT; ++it) {
        if (it + 1 < NIT) gload((it + 1) * 16);
        int buf = it & 1;
#pragma unroll
        for (int ks = 0; ks < 2; ++ks) {
            const int kk = ks * 8;
            uint32_t af[2][4];
#pragma unroll
            for (int mt = 0; mt < 2; ++mt) {
                int base = wm + mt * 16;
                af[mt][0] = As[buf][base + q][kk + r];
                af[mt][1] = As[buf][base + q + 8][kk + r];
                af[mt][2] = As[buf][base + q][kk + r + 4];
                af[mt][3] = As[buf][base + q + 8][kk + r + 4];
            }
#pragma unroll
            for (int nt = 0; nt < 8; ++nt) {
                uint32_t bf[2];
                bf[0] = Bsm[buf][wn + nt * 8 + q][kk + r];
                bf[1] = Bsm[buf][wn + nt * 8 + q][kk + r + 4];
                mma8(acc[0][nt], af[0], bf);
                mma8(acc[1][nt], af[1], bf);
            }
        }
        if (it + 1 < NIT) sstore(buf ^ 1, (it + 1) * 16);
        __syncthreads();
    }

#pragma unroll
    for (int mt = 0; mt < 2; ++mt) {
        int rowa = row0 + wm + mt * 16 + q;
#pragma unroll
        for (int nt = 0; nt < 8; ++nt) {
            int n = n0 + wn + nt * 8 + 2 * r;
            *(float2*)&g_xz[(size_t)rowa * 1024 + n]       = make_float2(acc[mt][nt][0], acc[mt][nt][1]);
            *(float2*)&g_xz[(size_t)(rowa + 8) * 1024 + n] = make_float2(acc[mt][nt][2], acc[mt][nt][3]);
        }
    }
}

// ---------------- 2. causal depthwise conv (k=4) + silu, rolling window ----------------
// grid = B * (L/8) blocks, 512 threads (=d). Each thread does 8 t's with a rolling window.
__global__ __launch_bounds__(512) void conv_silu_kernel(
    const float* __restrict__ conv_w, const float* __restrict__ conv_b) {
    int d  = threadIdx.x;
    int bb = blockIdx.x >> 7;
    int t0 = (blockIdx.x & 127) * 8;
    float4 w = *(const float4*)&conv_w[d * 4];
    float bias = conv_b[d];
    size_t base = (size_t)bb * L_ * 1024 + d;
    float xm3 = (t0 >= 3) ? g_xz[base + (size_t)(t0 - 3) * 1024] : 0.f;
    float xm2 = (t0 >= 2) ? g_xz[base + (size_t)(t0 - 2) * 1024] : 0.f;
    float xm1 = (t0 >= 1) ? g_xz[base + (size_t)(t0 - 1) * 1024] : 0.f;
#pragma unroll
    for (int i = 0; i < 8; ++i) {
        int t = t0 + i;
        float cur = g_xz[base + (size_t)t * 1024];
        float acc = bias + w.x * xm3 + w.y * xm2 + w.z * xm1 + w.w * cur;
        float sv  = acc / (1.f + __expf(-acc));
        g_xs[((size_t)(bb * L_ + t)) * D_IN + d] = sv;
        xm3 = xm2; xm2 = xm1; xm1 = cur;
    }
}

// ---------------- 3. fused xdbl + dt: xdbl = xs @ W_x; dt = softplus(dtr@W_dt + b_dt) ----------------
// block = 32 rows, 256 threads. Phase 1: xdbl (Bm/Cm straight to g_bc, dtr to smem).
// Phase 2: dt GEMM with W_dt staged in the same smem (reused).
__global__ __launch_bounds__(256) void xdbl_dt_kernel(
    const float* __restrict__ W_x, const float* __restrict__ W_dt,
    const float* __restrict__ b_dt) {
    __shared__ __align__(16) char sb[34816];
    float* xsT  = (float*)sb;            // phase1: [32][64]  (8KB)
    float* Wxs  = (float*)(sb + 8192);   // phase1: [64*48]   (12KB)
    float* Wd   = (float*)sb;            // phase2: [16][512] (32KB)
    float* dtrS = (float*)(sb + 32768);  // [32][16] (2KB) — disjoint from phase1 region

    int row0 = blockIdx.x * 32;
    int tid  = threadIdx.x;
    int rp = tid >> 4, jj = tid & 15;    // rows 2rp, 2rp+1
    float a[6] = {};
    for (int kc = 0; kc < 512; kc += 64) {
        __syncthreads();
#pragma unroll
        for (int i = 0; i < 3; ++i) {
            int e = tid + i * 256;
            ((float4*)Wxs)[e] = ((const float4*)(W_x + kc * 48))[e];
        }
#pragma unroll
        for (int i = 0; i < 2; ++i) {
            int e = tid + i * 256;
            int rr = e >> 4, k4 = e & 15;
            ((float4*)xsT)[rr * 16 + k4] =
                *(const float4*)&g_xs[(size_t)(row0 + rr) * D_IN + kc + k4 * 4];
        }
        __syncthreads();
#pragma unroll 4
        for (int k = 0; k < 64; ++k) {
            const float* w = &Wxs[k * 48 + jj];
            float w0 = w[0], w1 = w[16], w2 = w[32];
            float v0 = xsT[(2 * rp) * 64 + k];
            float v1 = xsT[(2 * rp + 1) * 64 + k];
            a[0] += v0 * w0; a[1] += v0 * w1; a[2] += v0 * w2;
            a[3] += v1 * w0; a[4] += v1 * w1; a[5] += v1 * w2;
        }
    }
    {
        size_t r0 = (size_t)(row0 + 2 * rp);
        g_bc[r0 * 32 + jj]            = a[1];
        g_bc[r0 * 32 + 16 + jj]       = a[2];
        g_bc[(r0 + 1) * 32 + jj]      = a[4];
        g_bc[(r0 + 1) * 32 + 16 + jj] = a[5];
        dtrS[(2 * rp) * 16 + jj]      = a[0];
        dtrS[(2 * rp + 1) * 16 + jj]  = a[3];
    }
    __syncthreads();
    // phase 2: stage W_dt (16x512 = 2048 float4 / 256 threads = 8 each)
#pragma unroll
    for (int i = 0; i < 8; ++i) {
        int e = tid + i * 256;
        ((float4*)Wd)[e] = ((const float4*)W_dt)[e];
    }
    __syncthreads();
    int row   = tid >> 3;        // 0..31
    int dbase = tid & 7;
    float dr[16];
#pragma unroll
    for (int j = 0; j < 16; ++j) dr[j] = dtrS[row * 16 + j];
    size_t orow = (size_t)(row0 + row) * D_IN;
#pragma unroll 4
    for (int k = 0; k < 64; ++k) {
        int dd = dbase + k * 8;
        float acc = b_dt[dd];
#pragma unroll
        for (int j = 0; j < 16; ++j) acc += dr[j] * Wd[j * 512 + dd];
        float sp = (acc > 20.f) ? acc : log1pf(__expf(acc));
        g_dt[orow + dd] = sp;
    }
}

// ---------------- 4. selective scan, smem-staged in 64-step chunks ----------------
#define TCH 64
__global__ __launch_bounds__(128) void scan_kernel(
    const float* __restrict__ A_log, const float* __restrict__ Dp) {
    __shared__ float s_dt[TCH][8];
    __shared__ float s_xs[TCH][8];
    __shared__ float s_z[TCH][8];
    __shared__ float s_bc[TCH][32];

    int blk   = blockIdx.x;
    int b     = blk >> 6;
    int chunk = blk & 63;
    int d0    = chunk * 8;
    int tid   = threadIdx.x;
    int warp  = tid >> 5;
    int lane  = tid & 31;
    int jd    = warp * 2 + (lane >> 4);   // 0..7 local channel
    int d     = d0 + jd;
    int s     = lane & 15;

    float A_ds = -__expf(A_log[d * D_ST + s]);
    float Dp_d = Dp[d];
    float h    = 0.f;
    size_t rowBase = (size_t)b * L_;

    for (int t0 = 0; t0 < L_; t0 += TCH) {
        __syncthreads();
#pragma unroll
        for (int i = 0; i < 4; ++i) {
            int e = tid + i * 128;
            int t = e >> 3, j = e & 7;
            size_t row = rowBase + t0 + t;
            s_dt[t][j] = g_dt[row * D_IN + d0 + j];
            s_xs[t][j] = g_xs[row * D_IN + d0 + j];
            s_z[t][j]  = g_xz[row * 1024 + 512 + d0 + j];
        }
#pragma unroll
        for (int i = 0; i < 16; ++i) {
            int e = tid + i * 128;
            int t = e >> 5, sj = e & 31;
            s_bc[t][sj] = g_bc[(rowBase + t0 + t) * 32 + sj];
        }
        __syncthreads();
#pragma unroll 4
        for (int tt = 0; tt < TCH; ++tt) {
            float dtv = s_dt[tt][jd];
            float xsv = s_xs[tt][jd];
            float Bm  = s_bc[tt][s];
            float Cm  = s_bc[tt][16 + s];
            h = __expf(dtv * A_ds) * h + (dtv * xsv) * Bm;
            float p = h * Cm;
            p += __shfl_xor_sync(0xffffffffu, p, 8);
            p += __shfl_xor_sync(0xffffffffu, p, 4);
            p += __shfl_xor_sync(0xffffffffu, p, 2);
            p += __shfl_xor_sync(0xffffffffu, p, 1);
            if (s == 0) {
                float zv = s_z[tt][jd];
                float y  = p + xsv * Dp_d;
                y = y * (zv / (1.f + __expf(-zv)));
                g_yact[(rowBase + t0 + tt) * D_IN + d] = y;
            }
        }
    }
}

// ---------------- 5. GEMM3 (tf32 mma.sync): out = yact @ W_out, transposed store ----------------
// M=8192, N=256, K=512. CTA 128x128, 8 warps, BK=16.
__global__ __launch_bounds__(256) void gemm3_mma_kernel(
    const float* __restrict__ W_out, float* __restrict__ out) {
    __shared__ uint32_t As[2][128][PAD];   // [m][k] tf32 bits
    __shared__ uint32_t Bsm[2][128][PAD];  // [n][k] tf32 bits

    const int tid  = threadIdx.x;
    const int wid  = tid >> 5;
    const int lane = tid & 31;
    const int n0   = blockIdx.x * 128;
    const int row0 = blockIdx.y * 128;
    const int b    = row0 >> 10;
    const int l0   = row0 & 1023;

    const int q = lane >> 2, r = lane & 3;
    const int wm = (wid >> 1) * 32, wn = (wid & 1) * 64;

    float ra[8], rb[8];
    auto gload = [&](int kc) {
#pragma unroll
        for (int i = 0; i < 8; ++i) {
            int e = tid + i * 256;
            int mA = e >> 4, kA = e & 15;
            ra[i] = g_yact[(size_t)(row0 + mA) * D_IN + kc + kA];
            int nB = e & 127, kB = e >> 7;
            rb[i] = W_out[(size_t)(kc + kB) * C_ + n0 + nB];
        }
    };
    auto sstore = [&](int buf) {
#pragma unroll
        for (int i = 0; i < 8; ++i) {
            int e = tid + i * 256;
            int mA = e >> 4, kA = e & 15;
            As[buf][mA][kA] = to_tf32(ra[i]);
            int nB = e & 127, kB = e >> 7;
            Bsm[buf][nB][kB] = to_tf32(rb[i]);
        }
    };

    float acc[2][8][4] = {};
    gload(0);
    sstore(0);
    __syncthreads();

    const int NIT = D_IN / 16;  // 32
    for (int it = 0; it < NIT; ++it) {
        if (it + 1 < NIT) gload((it + 1) * 16);
        int buf = it & 1;
#pragma unroll
        for (int ks = 0; ks < 2; ++ks) {
            const int kk = ks * 8;
            uint32_t af[2][4];
#pragma unroll
            for (int mt = 0; mt < 2; ++mt) {
                int base = wm + mt * 16;
                af[mt][0] = As[buf][base + q][kk + r];
                af[mt][1] = As[buf][base + q + 8][kk + r];
                af[mt][2] = As[buf][base + q][kk + r + 4];
                af[mt][3] = As[buf][base + q + 8][kk + r + 4];
            }
#pragma unroll
            for (int nt = 0; nt < 8; ++nt) {
                uint32_t bf[2];
                bf[0] = Bsm[buf][wn + nt * 8 + q][kk + r];
                bf[1] = Bsm[buf][wn + nt * 8 + q][kk + r + 4];
                mma8(acc[0][nt], af[0], bf);
                mma8(acc[1][nt], af[1], bf);
            }
        }
        if (it + 1 < NIT) sstore(buf ^ 1);
        __syncthreads();
    }

    // transposed store: out[(b*C + n)*L + l0 + m]
#pragma unroll
    for (int mt = 0; mt < 2; ++mt) {
        int m  = wm + mt * 16 + q;
#pragma unroll
        for (int nt = 0; nt < 8; ++nt) {
            int n = n0 + wn + nt * 8 + 2 * r;
            size_t p0 = (size_t)(b * C_ + n) * L_ + l0;
            size_t p1 = (size_t)(b * C_ + n + 1) * L_ + l0;
            out[p0 + m]     = acc[mt][nt][0];
            out[p1 + m]     = acc[mt][nt][1];
            out[p0 + m + 8] = acc[mt][nt][2];
            out[p1 + m + 8] = acc[mt][nt][3];
        }
    }
}

// ---------------- launch ----------------
extern "C" void kernel_launch(void* const* d_in, const int* in_sizes, int n_in,
                              void* d_out, int out_size) {
    const float* x      = (const float*)d_in[0];
    const float* ln_w   = (const float*)d_in[1];
    const float* ln_b   = (const float*)d_in[2];
    const float* W_in   = (const float*)d_in[3];
    const float* conv_w = (const float*)d_in[4];
    const float* conv_b = (const float*)d_in[5];
    const float* W_x    = (const float*)d_in[6];
    const float* W_dt   = (const float*)d_in[7];
    const float* b_dt   = (const float*)d_in[8];
    const float* A_log  = (const float*)d_in[9];
    const float* Dp     = (const float*)d_in[10];
    const float* W_out  = (const float*)d_in[11];
    float* out = (float*)d_out;

    gemm1_mma_kernel<<<dim3(1024 / 128, BL / 128), 256>>>(x, ln_w, ln_b, W_in);
    conv_silu_kernel<<<B_ * (L_ / 8), 512>>>(conv_w, conv_b);
    xdbl_dt_kernel<<<BL / 32, 256>>>(W_x, W_dt, b_dt);
    scan_kernel<<<512, 128>>>(A_log, Dp);
    gemm3_mma_kernel<<<dim3(C_ / 128, BL / 128), 256>>>(W_out, out);
}